// round 5
// baseline (speedup 1.0000x reference)
#include <cuda_runtime.h>
#include <cuda_bf16.h>
#include <cstdint>

#define DINLINE __device__ __forceinline__

// ---------------- scratch (device globals; no runtime allocation) ----------
__device__ float g_partial[4096];
__device__ float g_alpha;
__device__ float g_scales[4096];                        // alpha*gamma/127 per token
__device__ __align__(128) unsigned char g_wq[16777216]; // ternary W as s8, [N,K]
__device__ __align__(128) unsigned char g_xq[16777216]; // quantized x as s8, [M,K]

// ---------------- PTX helpers (baseline ISA only: sm_80-compatible) --------
DINLINE uint32_t smem_u32(const void* p) {
    uint32_t a;
    asm("{ .reg .u64 t; cvta.to.shared.u64 t, %1; cvt.u32.u64 %0, t; }"
        : "=r"(a) : "l"(p));
    return a;
}
DINLINE void cp16(uint32_t dst, const void* src) {
    asm volatile("cp.async.cg.shared.global [%0], [%1], 16;" :: "r"(dst), "l"(src));
}
DINLINE void cp_commit() { asm volatile("cp.async.commit_group;" ::: "memory"); }
DINLINE void cp_wait2()  { asm volatile("cp.async.wait_group 2;" ::: "memory"); }

DINLINE void ldsm_x4(uint32_t& r0, uint32_t& r1, uint32_t& r2, uint32_t& r3, uint32_t addr) {
    asm volatile("ldmatrix.sync.aligned.m8n8.x4.shared.b16 {%0,%1,%2,%3}, [%4];"
                 : "=r"(r0), "=r"(r1), "=r"(r2), "=r"(r3) : "r"(addr));
}
DINLINE void mma_s8(int* c, uint32_t a0, uint32_t a1, uint32_t a2, uint32_t a3,
                    uint32_t b0, uint32_t b1) {
    asm volatile(
        "mma.sync.aligned.m16n8k32.row.col.s32.s8.s8.s32 "
        "{%0,%1,%2,%3}, {%4,%5,%6,%7}, {%8,%9}, {%0,%1,%2,%3};"
        : "+r"(c[0]), "+r"(c[1]), "+r"(c[2]), "+r"(c[3])
        : "r"(a0), "r"(a1), "r"(a2), "r"(a3), "r"(b0), "r"(b1));
}
DINLINE int clampi(int v, int lo, int hi) { return v < lo ? lo : (v > hi ? hi : v); }
DINLINE uint32_t pack4(int q0, int q1, int q2, int q3) {
    return (uint32_t)(q0 & 0xFF) | ((uint32_t)(q1 & 0xFF) << 8) |
           ((uint32_t)(q2 & 0xFF) << 16) | ((uint32_t)(q3 & 0xFF) << 24);
}

// ---------------- kernel 1: per-block |W| partial sums ----------------------
__global__ void __launch_bounds__(256) k_abs_partial(const float4* __restrict__ w) {
    __shared__ float red[256];
    const int b = blockIdx.x, t = threadIdx.x;
    const float4* p = w + (size_t)b * 1024;
    float s = 0.f;
#pragma unroll
    for (int i = 0; i < 4; i++) {
        float4 v = p[t + 256 * i];
        s += fabsf(v.x) + fabsf(v.y) + fabsf(v.z) + fabsf(v.w);
    }
    red[t] = s; __syncthreads();
#pragma unroll
    for (int o = 128; o > 0; o >>= 1) { if (t < o) red[t] += red[t + o]; __syncthreads(); }
    if (t == 0) g_partial[b] = red[0];
}

// ---------------- kernel 2: finalize alpha ----------------------------------
__global__ void __launch_bounds__(256) k_alpha_final() {
    __shared__ float red[256];
    const int t = threadIdx.x;
    float s = 0.f;
    for (int i = t; i < 4096; i += 256) s += g_partial[i];
    red[t] = s; __syncthreads();
#pragma unroll
    for (int o = 128; o > 0; o >>= 1) { if (t < o) red[t] += red[t + o]; __syncthreads(); }
    if (t == 0) g_alpha = fmaxf(red[0] * (1.0f / 16777216.0f), 1e-10f);
}

// ---------------- kernel 3: ternary-quantize W to s8 ------------------------
__global__ void __launch_bounds__(256) k_quant_w(const float4* __restrict__ w) {
    const float inv_alpha = 1.0f / g_alpha;
    const int idx = blockIdx.x * 256 + threadIdx.x;   // float4 index, 4194304 total
    float4 v = w[idx];
    int q0 = clampi(__float2int_rn(v.x * inv_alpha), -1, 1);
    int q1 = clampi(__float2int_rn(v.y * inv_alpha), -1, 1);
    int q2 = clampi(__float2int_rn(v.z * inv_alpha), -1, 1);
    int q3 = clampi(__float2int_rn(v.w * inv_alpha), -1, 1);
    reinterpret_cast<uint32_t*>(g_wq)[idx] = pack4(q0, q1, q2, q3);
}

// ---------------- kernel 4: RMSNorm + per-token int8 quantize ---------------
__global__ void __launch_bounds__(256) k_quant_x(const float* __restrict__ x,
                                                 const float* __restrict__ nw) {
    __shared__ float sx[4096];
    __shared__ float red[256];
    const int m = blockIdx.x, t = threadIdx.x;
    const float4* xr = reinterpret_cast<const float4*>(x + (size_t)m * 4096);
    float ss = 0.f;
#pragma unroll
    for (int i = 0; i < 4; i++) {
        float4 v = xr[t + 256 * i];
        reinterpret_cast<float4*>(sx)[t + 256 * i] = v;
        ss += v.x * v.x + v.y * v.y + v.z * v.z + v.w * v.w;
    }
    red[t] = ss; __syncthreads();
#pragma unroll
    for (int o = 128; o > 0; o >>= 1) { if (t < o) red[t] += red[t + o]; __syncthreads(); }
    const float rinv = 1.0f / sqrtf(red[0] * (1.0f / 4096.0f) + 1e-6f);
    __syncthreads();

    const float4* nwr = reinterpret_cast<const float4*>(nw);
    float mx = 0.f;
#pragma unroll
    for (int i = 0; i < 4; i++) {
        float4 v = reinterpret_cast<float4*>(sx)[t + 256 * i];
        float4 g = nwr[t + 256 * i];
        v.x *= rinv * g.x; v.y *= rinv * g.y; v.z *= rinv * g.z; v.w *= rinv * g.w;
        reinterpret_cast<float4*>(sx)[t + 256 * i] = v;
        mx = fmaxf(mx, fmaxf(fmaxf(fabsf(v.x), fabsf(v.y)), fmaxf(fabsf(v.z), fabsf(v.w))));
    }
    red[t] = mx; __syncthreads();
#pragma unroll
    for (int o = 128; o > 0; o >>= 1) { if (t < o) red[t] = fmaxf(red[t], red[t + o]); __syncthreads(); }
    const float gamma = fmaxf(red[0], 1e-10f);
    if (t == 0) g_scales[m] = g_alpha * gamma * (1.0f / 127.0f);
    const float qs = 127.0f / gamma;
    uint32_t* dst = reinterpret_cast<uint32_t*>(g_xq) + (size_t)m * 1024;
#pragma unroll
    for (int i = 0; i < 4; i++) {
        float4 v = reinterpret_cast<float4*>(sx)[t + 256 * i];
        int q0 = clampi(__float2int_rn(v.x * qs), -128, 127);
        int q1 = clampi(__float2int_rn(v.y * qs), -128, 127);
        int q2 = clampi(__float2int_rn(v.z * qs), -128, 127);
        int q3 = clampi(__float2int_rn(v.w * qs), -128, 127);
        dst[t + 256 * i] = pack4(q0, q1, q2, q3);
    }
}

// ---------------- kernel 5: int8 IMMA GEMM + per-row rescale ----------------
// D[m, n] = sum_k xq[m,k] * wq[n,k]  (exact in s32), y = D * scale[m]
// CTA tile 128x128, BK=64, 4-stage cp.async pipeline, 8 warps of 64x32.
static constexpr int BM = 128, BN = 128, BK = 64;
static constexpr int LDS_PAD = 80;                 // padded row stride (16B mult, bank-safe)
static constexpr int ASIZE = BM * LDS_PAD;         // 10240 bytes
static constexpr int STAGE = 2 * ASIZE;            // A + B = 20480 bytes
static constexpr int GEMM_SMEM = 4 * STAGE;        // 81920 bytes

__global__ void __launch_bounds__(256, 2) k_gemm(float* __restrict__ out) {
    extern __shared__ char smemraw[];
    const uint32_t sbase = smem_u32(smemraw);
    const int t = threadIdx.x;
    const int lane = t & 31, wid = t >> 5;
    const int warpM = wid >> 2;        // 0..1  -> 64-row slab
    const int warpN = wid & 3;         // 0..3  -> 32-col slab
    const int m0 = blockIdx.y * BM, n0 = blockIdx.x * BN;

    const char* gA = reinterpret_cast<const char*>(g_xq) + (size_t)m0 * 4096;
    const char* gB = reinterpret_cast<const char*>(g_wq) + (size_t)n0 * 4096;

    // loader coords: each thread copies rows r and r+64, 16B column c, for A and B
    const int lr = t >> 2;             // 0..63
    const int lc = (t & 3) * 16;       // 0,16,32,48

    // ldmatrix per-thread address components (x4 over 16 rows x 32 bytes)
    const int xrow = (lane & 7) + ((lane >> 3) & 1) * 8;
    const int xcol = (lane >> 4) * 16;

    int acc[4][4][4];
#pragma unroll
    for (int i = 0; i < 4; i++)
#pragma unroll
        for (int j = 0; j < 4; j++)
#pragma unroll
            for (int q = 0; q < 4; q++) acc[i][j][q] = 0;

    auto load_stage = [&](int s, int k) {
        const uint32_t dst = sbase + s * STAGE;
        const char* sA = gA + (size_t)k * BK;
        const char* sB = gB + (size_t)k * BK;
        const uint32_t dA = dst + lr * LDS_PAD + lc;
        cp16(dA,                   sA + (size_t)lr * 4096 + lc);
        cp16(dA + 64 * LDS_PAD,    sA + (size_t)(lr + 64) * 4096 + lc);
        const uint32_t dB = dst + ASIZE + lr * LDS_PAD + lc;
        cp16(dB,                   sB + (size_t)lr * 4096 + lc);
        cp16(dB + 64 * LDS_PAD,    sB + (size_t)(lr + 64) * 4096 + lc);
    };

    // prologue: stages 0..2
#pragma unroll
    for (int k = 0; k < 3; k++) { load_stage(k, k); cp_commit(); }

    for (int k = 0; k < 64; k++) {
        cp_wait2();                 // stage k's group has landed
        __syncthreads();            // all warps done computing stage k-1; data visible

        const int kn = k + 3;
        if (kn < 64) load_stage(kn & 3, kn);
        cp_commit();                // uniform group count

        const uint32_t stA = sbase + (k & 3) * STAGE;
        const uint32_t stB = stA + ASIZE;
#pragma unroll
        for (int kk = 0; kk < 2; kk++) {
            uint32_t a[4][4];
#pragma unroll
            for (int i = 0; i < 4; i++)
                ldsm_x4(a[i][0], a[i][1], a[i][2], a[i][3],
                        stA + (warpM * 64 + i * 16 + xrow) * LDS_PAD + kk * 32 + xcol);
            uint32_t b[4][2];
#pragma unroll
            for (int j2 = 0; j2 < 2; j2++) {
                uint32_t q0, q1, q2, q3;
                ldsm_x4(q0, q1, q2, q3,
                        stB + (warpN * 32 + j2 * 16 + xrow) * LDS_PAD + kk * 32 + xcol);
                b[2 * j2][0] = q0; b[2 * j2 + 1][0] = q1;
                b[2 * j2][1] = q2; b[2 * j2 + 1][1] = q3;
            }
#pragma unroll
            for (int i = 0; i < 4; i++)
#pragma unroll
                for (int j = 0; j < 4; j++)
                    mma_s8(acc[i][j], a[i][0], a[i][1], a[i][2], a[i][3], b[j][0], b[j][1]);
        }
    }

    // epilogue: scale by per-row alpha*gamma/127 and store fp32
    const int rq = lane >> 2;
    const int cq = (lane & 3) * 2;
    const int nw = n0 + warpN * 32 + cq;
#pragma unroll
    for (int i = 0; i < 4; i++) {
        const int row = m0 + warpM * 64 + i * 16 + rq;
        const float s0 = g_scales[row];
        const float s1 = g_scales[row + 8];
        float* o0 = out + (size_t)row * 4096 + nw;
        float* o1 = o0 + (size_t)8 * 4096;
#pragma unroll
        for (int j = 0; j < 4; j++) {
            float2 v0; v0.x = (float)acc[i][j][0] * s0; v0.y = (float)acc[i][j][1] * s0;
            *reinterpret_cast<float2*>(o0 + j * 8) = v0;
            float2 v1; v1.x = (float)acc[i][j][2] * s1; v1.y = (float)acc[i][j][3] * s1;
            *reinterpret_cast<float2*>(o1 + j * 8) = v1;
        }
    }
}

// ---------------- launch -----------------------------------------------------
extern "C" void kernel_launch(void* const* d_in, const int* in_sizes, int n_in,
                              void* d_out, int out_size) {
    (void)in_sizes; (void)n_in; (void)out_size;
    const float* x  = reinterpret_cast<const float*>(d_in[0]);   // [2,2048,4096]
    const float* w  = reinterpret_cast<const float*>(d_in[1]);   // [4096,4096]
    const float* nw = reinterpret_cast<const float*>(d_in[2]);   // [4096]
    float* y = reinterpret_cast<float*>(d_out);                  // [2,2048,4096]

    static bool attr_set = false;
    if (!attr_set) {
        cudaFuncSetAttribute(k_gemm, cudaFuncAttributeMaxDynamicSharedMemorySize, GEMM_SMEM);
        attr_set = true;
    }

    k_abs_partial<<<4096, 256>>>(reinterpret_cast<const float4*>(w));
    k_alpha_final<<<1, 256>>>();
    k_quant_w<<<16384, 256>>>(reinterpret_cast<const float4*>(w));
    k_quant_x<<<4096, 256>>>(x, nw);
    k_gemm<<<dim3(32, 32), 256, GEMM_SMEM>>>(y);
}